// round 11
// baseline (speedup 1.0000x reference)
#include <cuda_runtime.h>
#include <cuda_fp16.h>
#include <cstdint>

// Problem shape: B=4, H=16, L=4096, D=64, S=128
#define B_ 4
#define H_ 16
#define L_ 4096
#define D_ 64
#define S_ 128

// Precomputed fp16 codebook hi/lo splits, SW128-swizzled, 16KB per head each.
__device__ uint4 g_cf16[2][H_][1024];

__device__ __forceinline__ uint32_t smem_to_u32(const void* p) {
    uint32_t a;
    asm("{ .reg .u64 t; cvta.to.shared.u64 t, %1; cvt.u32.u64 %0, t; }"
        : "=r"(a) : "l"(p));
    return a;
}
__device__ __forceinline__ uint32_t swz(uint32_t off) {   // SW128, 16B granules
    return off ^ ((off >> 3) & 0x70);
}
__device__ __forceinline__ void ldsm_x4(uint32_t a, uint32_t r[4]) {
    asm volatile("ldmatrix.sync.aligned.m8n8.x4.shared.b16 {%0,%1,%2,%3}, [%4];"
                 : "=r"(r[0]), "=r"(r[1]), "=r"(r[2]), "=r"(r[3]) : "r"(a));
}
__device__ __forceinline__ void mma_f16(float d[4], const uint32_t a[4],
                                        uint32_t b0, uint32_t b1) {
    asm volatile(
        "mma.sync.aligned.m16n8k16.row.col.f32.f16.f16.f32 "
        "{%0,%1,%2,%3}, {%4,%5,%6,%7}, {%8,%9}, {%0,%1,%2,%3};"
        : "+f"(d[0]), "+f"(d[1]), "+f"(d[2]), "+f"(d[3])
        : "r"(a[0]), "r"(a[1]), "r"(a[2]), "r"(a[3]), "r"(b0), "r"(b1));
}

// Split 8 floats -> hi-fp16 uint4 + lo-fp16 uint4 (x = hi + lo to ~2^-22)
__device__ __forceinline__ void split8_f16(const float f[8], uint4& hi, uint4& lo) {
    uint32_t w1[4], w2[4];
    #pragma unroll
    for (int k = 0; k < 4; ++k) {
        const __half a1 = __float2half_rn(f[2*k]);
        const __half a2 = __float2half_rn(f[2*k]   - __half2float(a1));
        const __half b1 = __float2half_rn(f[2*k+1]);
        const __half b2 = __float2half_rn(f[2*k+1] - __half2float(b1));
        w1[k] = (uint32_t)__half_as_ushort(a1) | ((uint32_t)__half_as_ushort(b1) << 16);
        w2[k] = (uint32_t)__half_as_ushort(a2) | ((uint32_t)__half_as_ushort(b2) << 16);
    }
    hi = make_uint4(w1[0], w1[1], w1[2], w1[3]);
    lo = make_uint4(w2[0], w2[1], w2[2], w2[3]);
}

// ---------- presplit: c -> fp16 hi/lo swizzled global + out-tail copy ----------
__global__ void presplit_c_kernel(const float* __restrict__ c,
                                  float4* __restrict__ out_tail) {
    const int chunk = blockIdx.x * 256 + threadIdx.x;   // 16384 chunks of 8 floats
    const int h  = chunk >> 10;
    const int cr = (chunk >> 3) & 127;
    const int cc = chunk & 7;
    const float4* src = reinterpret_cast<const float4*>(
        c + (size_t)h * S_ * D_ + cr * 64 + cc * 8);
    const float4 v0 = src[0], v1 = src[1];
    float f[8] = {v0.x, v0.y, v0.z, v0.w, v1.x, v1.y, v1.z, v1.w};
    uint4 hi, lo;
    split8_f16(f, hi, lo);
    const uint32_t idx = swz((uint32_t)(cr * 128 + cc * 16)) >> 4;
    g_cf16[0][h][idx] = hi;
    g_cf16[1][h][idx] = lo;
    // pass-through second output (c verbatim)
    out_tail[chunk * 2]     = v0;
    out_tail[chunk * 2 + 1] = v1;
}

// ---------------- smem layout (bytes) ----------------
#define SM_X1     0          // 16384  x hi fp16 (SW128)
#define SM_X2     16384      // 16384  x lo fp16 (SW128)
#define SM_C1     32768      // 16384  c hi fp16 (SW128)
#define SM_C2     49152      // 16384  c lo fp16 (SW128)
#define SM_XN2    65536      // 128 f32
#define SM_S1     66048      // 2*128 f32
#define SM_I1     67072      // 2*128 i32
#define SM_S2     68096      // 2*128 f32
#define SM_FIDX   69120      // 128 i32
#define SM_FLAG   69632      // 128 i32 (flagged-token list)
#define SM_NF     70144      // counter
#define SM_TOTAL  70160

__global__ __launch_bounds__(256, 3)
void quant_hmma_kernel(const float* __restrict__ x,
                       const float* __restrict__ c,
                       float* __restrict__ out) {
    extern __shared__ char smem[];
    const uint32_t sb = smem_to_u32(smem);
    const int tid = threadIdx.x, wid = tid >> 5, lane = tid & 31;
    const int bh = blockIdx.y, h = bh & (H_ - 1);
    const size_t tok0 = (size_t)bh * L_ + (size_t)blockIdx.x * 128;

    float* sm_xn2 = reinterpret_cast<float*>(smem + SM_XN2);
    float* sm_s1  = reinterpret_cast<float*>(smem + SM_S1);
    int*   sm_i1  = reinterpret_cast<int*>(smem + SM_I1);
    float* sm_s2  = reinterpret_cast<float*>(smem + SM_S2);
    int*   sm_fi  = reinterpret_cast<int*>(smem + SM_FIDX);
    int*   sm_fl  = reinterpret_cast<int*>(smem + SM_FLAG);
    int*   sm_nf  = reinterpret_cast<int*>(smem + SM_NF);

    if (tid == 0) *sm_nf = 0;

    // --- copy precomputed fp16 codebook tiles (already swizzled) into smem ---
    {
        const uint4* g1 = g_cf16[0][h];
        const uint4* g2 = g_cf16[1][h];
        uint4* d1 = reinterpret_cast<uint4*>(smem + SM_C1);
        uint4* d2 = reinterpret_cast<uint4*>(smem + SM_C2);
        #pragma unroll
        for (int i = tid; i < 1024; i += 256) { d1[i] = g1[i]; d2[i] = g2[i]; }
    }

    // --- x tile [128 x 64] -> fp16 hi/lo SW128 smem + per-token ||x||^2 ---
    {
        const float* xg = x + tok0 * D_;
        #pragma unroll
        for (int it = 0; it < 4; ++it) {
            const int j = tid + it * 256;
            const int row = j >> 3, cc = j & 7;
            const float4* src = reinterpret_cast<const float4*>(xg + row * 64 + cc * 8);
            const float4 v0 = src[0], v1 = src[1];
            float f[8] = {v0.x, v0.y, v0.z, v0.w, v1.x, v1.y, v1.z, v1.w};
            float nrm = 0.f;
            #pragma unroll
            for (int e = 0; e < 8; ++e) nrm = fmaf(f[e], f[e], nrm);
            nrm += __shfl_xor_sync(0xffffffffu, nrm, 1);
            nrm += __shfl_xor_sync(0xffffffffu, nrm, 2);
            nrm += __shfl_xor_sync(0xffffffffu, nrm, 4);
            if ((lane & 7) == 0) sm_xn2[row] = nrm;
            uint4 hi, lo;
            split8_f16(f, hi, lo);
            const uint32_t off = swz((uint32_t)(row*128 + cc*16));
            *reinterpret_cast<uint4*>(smem + SM_X1 + off) = hi;
            *reinterpret_cast<uint4*>(smem + SM_X2 + off) = lo;
        }
    }
    __syncthreads();

    // --- MMA: warp -> tokens [32*(wid>>1), +32), codes [64*(wid&1), +64),
    //     two nb-half passes; 3 product passes folded per k:
    //     x1*c1 + x1*c2 + x2*c1  (error ~1e-6*||x||) ---
    const int tb = wid >> 1;
    const int ch = wid & 1;

    const int arow = lane & 15, acol = lane >> 4;
    const int brow_base = ch * 64 + ((lane >> 4) << 3) + (lane & 7);
    const int bcol = (lane >> 3) & 1;
    const int g = (lane >> 2) & 7, tig = lane & 3;

    float s1[4], s2[4];
    int   i1[4];
    #pragma unroll
    for (int t = 0; t < 4; ++t) {
        s1[t] = -3.402823466e38f; s2[t] = -3.402823466e38f; i1[t] = 0;
    }

    #pragma unroll 1
    for (int pass = 0; pass < 2; ++pass) {
        float d[2][4][4];
        #pragma unroll
        for (int m = 0; m < 2; ++m)
            #pragma unroll
            for (int nb = 0; nb < 4; ++nb)
                #pragma unroll
                for (int q = 0; q < 4; ++q) d[m][nb][q] = 0.f;

        #pragma unroll
        for (int k = 0; k < 4; ++k) {
            uint32_t a1f[2][4], a2f[2][4];
            #pragma unroll
            for (int m = 0; m < 2; ++m) {
                const uint32_t aoff =
                    swz((uint32_t)((tb*32 + m*16 + arow)*128 + (2*k + acol)*16));
                ldsm_x4(sb + SM_X1 + aoff, a1f[m]);
                ldsm_x4(sb + SM_X2 + aoff, a2f[m]);
            }
            #pragma unroll
            for (int nbl = 0; nbl < 2; ++nbl) {
                const int nbp = pass * 2 + nbl;
                const uint32_t boff =
                    swz((uint32_t)((brow_base + nbp*16)*128 + (2*k + bcol)*16));
                uint32_t b1f[4], b2f[4];
                ldsm_x4(sb + SM_C1 + boff, b1f);
                ldsm_x4(sb + SM_C2 + boff, b2f);
                #pragma unroll
                for (int m = 0; m < 2; ++m) {
                    mma_f16(d[m][2*nbl],   a1f[m], b1f[0], b1f[1]);
                    mma_f16(d[m][2*nbl],   a1f[m], b2f[0], b2f[1]);
                    mma_f16(d[m][2*nbl],   a2f[m], b1f[0], b1f[1]);
                    mma_f16(d[m][2*nbl+1], a1f[m], b1f[2], b1f[3]);
                    mma_f16(d[m][2*nbl+1], a1f[m], b2f[2], b2f[3]);
                    mma_f16(d[m][2*nbl+1], a2f[m], b1f[2], b1f[3]);
                }
            }
        }

        // fold this pass's 8 scores/token into running top2 (nb ascending)
        #pragma unroll
        for (int m = 0; m < 2; ++m) {
            #pragma unroll
            for (int r = 0; r < 2; ++r) {
                const int t = m * 2 + r;
                #pragma unroll
                for (int nbl = 0; nbl < 4; ++nbl) {
                    #pragma unroll
                    for (int col = 0; col < 2; ++col) {
                        const float s = d[m][nbl][2*r + col];
                        const int nb = pass * 4 + nbl;
                        const int ix = ch * 64 + nb * 8 + 2 * tig + col;
                        if (s > s1[t]) { s2[t] = s1[t]; s1[t] = s; i1[t] = ix; }
                        else if (s > s2[t]) s2[t] = s;
                    }
                }
            }
        }
    }

    // --- quad merge (lanes sharing token rows) ---
    #pragma unroll
    for (int off = 1; off <= 2; off <<= 1) {
        #pragma unroll
        for (int t = 0; t < 4; ++t) {
            const float os1 = __shfl_xor_sync(0xffffffffu, s1[t], off);
            const int   oi1 = __shfl_xor_sync(0xffffffffu, i1[t], off);
            const float os2 = __shfl_xor_sync(0xffffffffu, s2[t], off);
            const bool better = (os1 > s1[t]) || (os1 == s1[t] && oi1 < i1[t]);
            if (better) { s2[t] = fmaxf(s1[t], os2); s1[t] = os1; i1[t] = oi1; }
            else        { s2[t] = fmaxf(s2[t], os1); }
        }
    }
    if (tig == 0) {
        #pragma unroll
        for (int m = 0; m < 2; ++m)
            #pragma unroll
            for (int r = 0; r < 2; ++r) {
                const int t = m * 2 + r;
                const int trow = tb * 32 + m * 16 + g + 8 * r;
                sm_s1[ch * 128 + trow] = s1[t];
                sm_i1[ch * 128 + trow] = i1[t];
                sm_s2[ch * 128 + trow] = s2[t];
            }
    }
    __syncthreads();

    // --- merge halves; build flagged-token LIST (gap < 2*eps) ---
    if (tid < 128) {
        const float a1 = sm_s1[tid], b1 = sm_s1[128 + tid];
        const int   ai = sm_i1[tid], bi = sm_i1[128 + tid];
        const float a2 = sm_s2[tid], b2 = sm_s2[128 + tid];
        float f1, f2; int fi;
        const bool abet = (a1 > b1) || (a1 == b1 && ai < bi);
        if (abet) { f1 = a1; fi = ai; f2 = fmaxf(a2, b1); }
        else      { f1 = b1; fi = bi; f2 = fmaxf(b2, a1); }
        sm_fi[tid] = fi;
        // analytic 3-pass fp16 bound ~1e-6*||x||; use ~50x margin
        const float eps = 5.0e-5f * sqrtf(sm_xn2[tid]) + 5.0e-5f;
        if (f1 - f2 < 2.f * eps) {
            const int pos = atomicAdd(sm_nf, 1);
            sm_fl[pos] = tid;
        }
    }
    __syncthreads();

    // --- exact fp32 rescore of flagged tokens (rare: ~0.3%), full 128 codes,
    //     c from gmem — numerically certified in R9 (rel_err 0.0) ---
    const int nf = *sm_nf;
    const float4* cg4 = reinterpret_cast<const float4*>(c + (size_t)h * S_ * D_);
    for (int f = wid; f < nf; f += 8) {
        const int t = sm_fl[f];
        const float4* xg4 = reinterpret_cast<const float4*>(x + (tok0 + t) * D_);
        float acc[4] = {0.f, 0.f, 0.f, 0.f};
        #pragma unroll
        for (int kk = 0; kk < 16; ++kk) {
            const float4 xv = xg4[kk];           // uniform -> broadcast
            #pragma unroll
            for (int q = 0; q < 4; ++q) {
                const float4 cv = __ldg(&cg4[(lane + 32 * q) * 16 + kk]);
                acc[q] = fmaf(xv.x, cv.x, acc[q]);
                acc[q] = fmaf(xv.y, cv.y, acc[q]);
                acc[q] = fmaf(xv.z, cv.z, acc[q]);
                acc[q] = fmaf(xv.w, cv.w, acc[q]);
            }
        }
        float best = acc[0];
        int   bi2  = lane;
        #pragma unroll
        for (int q = 1; q < 4; ++q) {
            const int code = lane + 32 * q;
            if (acc[q] > best) { best = acc[q]; bi2 = code; }  // ascending idx
        }
        #pragma unroll
        for (int off = 16; off > 0; off >>= 1) {
            const float os = __shfl_xor_sync(0xffffffffu, best, off);
            const int   oi = __shfl_xor_sync(0xffffffffu, bi2, off);
            if (os > best || (os == best && oi < bi2)) { best = os; bi2 = oi; }
        }
        if (lane == 0) sm_fi[t] = bi2;
    }
    __syncthreads();

    // --- one-hot write: warp w -> tokens [16w, +16), coalesced float4 ---
    float4* outv = reinterpret_cast<float4*>(out);
    #pragma unroll 4
    for (int j = 0; j < 16; ++j) {
        const int t = wid * 16 + j;
        const int idx = sm_fi[t];
        float4 v = make_float4(0.f, 0.f, 0.f, 0.f);
        const int r = idx - lane * 4;
        if      (r == 0) v.x = 1.f;
        else if (r == 1) v.y = 1.f;
        else if (r == 2) v.z = 1.f;
        else if (r == 3) v.w = 1.f;
        outv[(tok0 + t) * (S_ / 4) + lane] = v;
    }
}

extern "C" void kernel_launch(void* const* d_in, const int* in_sizes, int n_in,
                              void* d_out, int out_size) {
    const float* x = (const float*)d_in[0];   // [B,H,L,D] fp32
    const float* c = (const float*)d_in[1];   // [H,S,D]  fp32
    float* out = (float*)d_out;

    // c -> fp16 hi/lo swizzled global codebook + out-tail pass-through
    presplit_c_kernel<<<64, 256>>>(
        c, reinterpret_cast<float4*>(out + (size_t)B_ * H_ * L_ * S_));

    cudaFuncSetAttribute(quant_hmma_kernel,
                         cudaFuncAttributeMaxDynamicSharedMemorySize, SM_TOTAL);
    dim3 grid(L_ / 128, B_ * H_);             // (32, 64) = 2048 CTAs
    quant_hmma_kernel<<<grid, 256, SM_TOTAL>>>(x, c, out);
}